// round 10
// baseline (speedup 1.0000x reference)
#include <cuda_runtime.h>
#include <cstdint>

// MeanAggregator: out[n,:] = mean over valid neighbors of features[idx[n,k],:]
// features: [60000,128] f32 (30.7MB, L2-resident). idx: [10000,64] (int64 or
// int32 per harness). mask: [10000,64] (byte or int32). out: [10000,128] f32.
//
// One warp per node, lane l owns dims [4l,4l+4) (16B) loaded as ulonglong2
// (LDG.128). Valid neighbor indices are warp-compacted into smem, then
// gathered 8 loads at a time; the dual accumulate paths keep all 8 loads
// live across the branch, forcing ptxas to front-batch the 8 LDG.128s
// (MLP=8 -- measured 18.0us vs 20.3us single-path). Accumulation uses
// packed f32x2 adds/FMAs (Blackwell FFMA2, PTX-only) to halve the FP
// instruction count in the hot loop.

#define K_NEIGH 64
#define D_VEC   32
#define WARPS_PER_BLOCK 8

__device__ __forceinline__ void addx2(unsigned long long& a, unsigned long long b) {
    asm("add.rn.f32x2 %0, %1, %2;" : "=l"(a) : "l"(a), "l"(b));
}
__device__ __forceinline__ void fmax2(unsigned long long& a, unsigned long long f,
                                      unsigned long long w) {
    asm("fma.rn.f32x2 %0, %1, %2, %3;" : "=l"(a) : "l"(f), "l"(w), "l"(a));
}
__device__ __forceinline__ void mulx2(unsigned long long& a, unsigned long long b) {
    asm("mul.rn.f32x2 %0, %1, %2;" : "=l"(a) : "l"(a), "l"(b));
}
__device__ __forceinline__ unsigned long long packf2(float x) {
    unsigned long long r;
    asm("mov.b64 %0, {%1, %1};" : "=l"(r) : "f"(x));
    return r;
}

__global__ __launch_bounds__(256) void mean_agg_kernel(
    const ulonglong2* __restrict__ feat,   // [60000, 32] x 16B
    const void* __restrict__ nidx,
    const void* __restrict__ nmask,
    ulonglong2* __restrict__ out,          // [n_nodes, 32] x 16B
    int n_nodes)
{
    __shared__ int srows[WARPS_PER_BLOCK][K_NEIGH];

    const int warp  = threadIdx.x >> 5;
    const int lane  = threadIdx.x & 31;
    const int gwarp = blockIdx.x * WARPS_PER_BLOCK + warp;
    if (gwarp >= n_nodes) return;

    // ---- Inline dtype detection (probes hit L1/L2 after first block) ----
    const int* iw = (const int*)nidx;
    int v = 0;
    #pragma unroll
    for (int r = 0; r < 4; r++) v |= iw[2 * (lane + 32 * r) + 1];
    const int idx_is64 = (__ballot_sync(0xffffffffu, v != 0) == 0);

    const unsigned char* mbp = (const unsigned char*)nmask;
    int mm = 0;
    #pragma unroll
    for (int r = 0; r < 4; r++) {
        int p = lane + 32 * r;
        if ((p & 3) != 0) mm |= mbp[p];
    }
    const int mask_is32 = (__ballot_sync(0xffffffffu, mm != 0) == 0);

    const size_t base = (size_t)gwarp * K_NEIGH;

    int i0, i1;
    if (idx_is64) {
        const long long* p = (const long long*)nidx + base;
        i0 = (int)p[lane]; i1 = (int)p[lane + 32];
    } else {
        const int* p = (const int*)nidx + base;
        i0 = p[lane]; i1 = p[lane + 32];
    }

    int m0, m1;
    if (mask_is32) {
        const int* p = (const int*)nmask + base;
        m0 = (p[lane] != 0); m1 = (p[lane + 32] != 0);
    } else {
        const unsigned char* p = (const unsigned char*)nmask + base;
        m0 = (p[lane] != 0); m1 = (p[lane + 32] != 0);
    }

    const unsigned b0 = __ballot_sync(0xffffffffu, m0);
    const unsigned b1 = __ballot_sync(0xffffffffu, m1);
    const int c0 = __popc(b0);
    const int cnt = c0 + __popc(b1);
    const unsigned lt = (1u << lane) - 1u;

    if (cnt == 0) {
        out[(size_t)gwarp * D_VEC + lane] = make_ulonglong2(0ull, 0ull);
        return;
    }

    // Pad slots alias row 0 (zeroed by tail weights).
    srows[warp][lane] = 0;
    srows[warp][lane + 32] = 0;
    __syncwarp();
    if (m0) srows[warp][__popc(b0 & lt)] = i0;
    if (m1) srows[warp][c0 + __popc(b1 & lt)] = i1;
    __syncwarp();

    // 4 accumulator slots x 2 packed f32x2 halves.
    unsigned long long acc[8];
    #pragma unroll
    for (int i = 0; i < 8; i++) acc[i] = 0ull;

    const int cnt8 = (cnt + 7) & ~7;

    // Prefetch first chunk's indices.
    int r0 = srows[warp][0], r1 = srows[warp][1];
    int r2 = srows[warp][2], r3 = srows[warp][3];
    int r4 = srows[warp][4], r5 = srows[warp][5];
    int r6 = srows[warp][6], r7 = srows[warp][7];

    for (int j = 0; j < cnt8; j += 8) {
        // 8 independent gathers in flight per warp.
        ulonglong2 f0 = __ldg(&feat[(size_t)r0 * D_VEC + lane]);
        ulonglong2 f1 = __ldg(&feat[(size_t)r1 * D_VEC + lane]);
        ulonglong2 f2 = __ldg(&feat[(size_t)r2 * D_VEC + lane]);
        ulonglong2 f3 = __ldg(&feat[(size_t)r3 * D_VEC + lane]);
        ulonglong2 f4 = __ldg(&feat[(size_t)r4 * D_VEC + lane]);
        ulonglong2 f5 = __ldg(&feat[(size_t)r5 * D_VEC + lane]);
        ulonglong2 f6 = __ldg(&feat[(size_t)r6 * D_VEC + lane]);
        ulonglong2 f7 = __ldg(&feat[(size_t)r7 * D_VEC + lane]);

        // Prefetch next chunk's indices while the gathers are in flight.
        if (j + 8 < cnt8) {
            r0 = srows[warp][j+8],  r1 = srows[warp][j+9];
            r2 = srows[warp][j+10], r3 = srows[warp][j+11];
            r4 = srows[warp][j+12], r5 = srows[warp][j+13];
            r6 = srows[warp][j+14], r7 = srows[warp][j+15];
        }

        if (j + 8 <= cnt) {   // warp-uniform: full chunk, packed pure adds
            addx2(acc[0], f0.x); addx2(acc[1], f0.y);
            addx2(acc[2], f1.x); addx2(acc[3], f1.y);
            addx2(acc[4], f2.x); addx2(acc[5], f2.y);
            addx2(acc[6], f3.x); addx2(acc[7], f3.y);
            addx2(acc[0], f4.x); addx2(acc[1], f4.y);
            addx2(acc[2], f5.x); addx2(acc[3], f5.y);
            addx2(acc[4], f6.x); addx2(acc[5], f6.y);
            addx2(acc[6], f7.x); addx2(acc[7], f7.y);
        } else {              // tail chunk: weight out the pads (packed FMA)
            unsigned long long w0 = packf2((j+0 < cnt) ? 1.f : 0.f);
            unsigned long long w1 = packf2((j+1 < cnt) ? 1.f : 0.f);
            unsigned long long w2 = packf2((j+2 < cnt) ? 1.f : 0.f);
            unsigned long long w3 = packf2((j+3 < cnt) ? 1.f : 0.f);
            unsigned long long w4 = packf2((j+4 < cnt) ? 1.f : 0.f);
            unsigned long long w5 = packf2((j+5 < cnt) ? 1.f : 0.f);
            unsigned long long w6 = packf2((j+6 < cnt) ? 1.f : 0.f);
            unsigned long long w7 = packf2((j+7 < cnt) ? 1.f : 0.f);
            fmax2(acc[0], f0.x, w0); fmax2(acc[1], f0.y, w0);
            fmax2(acc[2], f1.x, w1); fmax2(acc[3], f1.y, w1);
            fmax2(acc[4], f2.x, w2); fmax2(acc[5], f2.y, w2);
            fmax2(acc[6], f3.x, w3); fmax2(acc[7], f3.y, w3);
            fmax2(acc[0], f4.x, w4); fmax2(acc[1], f4.y, w4);
            fmax2(acc[2], f5.x, w5); fmax2(acc[3], f5.y, w5);
            fmax2(acc[4], f6.x, w6); fmax2(acc[5], f6.y, w6);
            fmax2(acc[6], f7.x, w7); fmax2(acc[7], f7.y, w7);
        }
    }

    // Reduce 4 slots -> 1, scale by 1/cnt (packed).
    addx2(acc[0], acc[2]); addx2(acc[1], acc[3]);
    addx2(acc[4], acc[6]); addx2(acc[5], acc[7]);
    addx2(acc[0], acc[4]); addx2(acc[1], acc[5]);
    const unsigned long long invp = packf2(1.0f / (float)cnt);
    mulx2(acc[0], invp);
    mulx2(acc[1], invp);

    out[(size_t)gwarp * D_VEC + lane] = make_ulonglong2(acc[0], acc[1]);
}

extern "C" void kernel_launch(void* const* d_in, const int* in_sizes, int n_in,
                              void* d_out, int out_size)
{
    const float* feat  = (const float*)d_in[0];
    const void*  nidx  = d_in[1];
    const void*  nmask = d_in[2];

    int n_nodes = in_sizes[1] / K_NEIGH;   // 10000

    const int threads = 32 * WARPS_PER_BLOCK;
    int blocks = (n_nodes + WARPS_PER_BLOCK - 1) / WARPS_PER_BLOCK;
    mean_agg_kernel<<<blocks, threads>>>(
        (const ulonglong2*)feat, nidx, nmask, (ulonglong2*)d_out, n_nodes);
}

// round 11
// speedup vs baseline: 1.0035x; 1.0035x over previous
#include <cuda_runtime.h>
#include <cstdint>

// MeanAggregator: out[n,:] = mean over valid neighbors of features[idx[n,k],:]
// features: [60000,128] f32 (30.7MB, L2-resident). idx: [10000,64] (int64 or
// int32 per harness). mask: [10000,64] (byte or int32). out: [10000,128] f32.
//
// One warp per node, lane l owns dims [4l,4l+4) as float4 (one LDG.128,
// coalesced 512B/row). Valid neighbor indices are warp-compacted into smem.
// Main loop covers only FULL 8-row chunks; the dual consumer arms (pure-add
// vs weighted) keep all 8 loaded float4s live across the branch, forcing
// ptxas to front-batch the 8 LDG.128s (MLP=8 -- measured 18.0us vs 20.3us
// single-path). The <=7-row tail uses predicated loads (warp-uniform @P LDG,
// zero traffic when off), eliminating ~9% of L2 traffic that pad rows cost.

#define K_NEIGH 64
#define D_VEC   32
#define WARPS_PER_BLOCK 8

__global__ __launch_bounds__(256) void mean_agg_kernel(
    const float4* __restrict__ feat,
    const void* __restrict__ nidx,
    const void* __restrict__ nmask,
    float4* __restrict__ out,
    int n_nodes)
{
    __shared__ int srows[WARPS_PER_BLOCK][K_NEIGH];

    const int warp  = threadIdx.x >> 5;
    const int lane  = threadIdx.x & 31;
    const int gwarp = blockIdx.x * WARPS_PER_BLOCK + warp;
    if (gwarp >= n_nodes) return;

    // ---- Inline dtype detection (probes are L2-hot after first block) ----
    const int* iw = (const int*)nidx;
    int v = 0;
    #pragma unroll
    for (int r = 0; r < 4; r++) v |= iw[2 * (lane + 32 * r) + 1];
    const int idx_is64 = (__ballot_sync(0xffffffffu, v != 0) == 0);

    const unsigned char* mbp = (const unsigned char*)nmask;
    int mm = 0;
    #pragma unroll
    for (int r = 0; r < 4; r++) {
        int p = lane + 32 * r;
        if ((p & 3) != 0) mm |= mbp[p];
    }
    const int mask_is32 = (__ballot_sync(0xffffffffu, mm != 0) == 0);

    const size_t base = (size_t)gwarp * K_NEIGH;

    int i0, i1;
    if (idx_is64) {
        const long long* p = (const long long*)nidx + base;
        i0 = (int)p[lane]; i1 = (int)p[lane + 32];
    } else {
        const int* p = (const int*)nidx + base;
        i0 = p[lane]; i1 = p[lane + 32];
    }

    int m0, m1;
    if (mask_is32) {
        const int* p = (const int*)nmask + base;
        m0 = (p[lane] != 0); m1 = (p[lane + 32] != 0);
    } else {
        const unsigned char* p = (const unsigned char*)nmask + base;
        m0 = (p[lane] != 0); m1 = (p[lane + 32] != 0);
    }

    const unsigned b0 = __ballot_sync(0xffffffffu, m0);
    const unsigned b1 = __ballot_sync(0xffffffffu, m1);
    const int c0  = __popc(b0);
    const int cnt = c0 + __popc(b1);

    if (cnt == 0) {
        out[(size_t)gwarp * D_VEC + lane] = make_float4(0.f, 0.f, 0.f, 0.f);
        return;
    }

    // Warp-compact valid indices into smem.
    const unsigned lt = (1u << lane) - 1u;
    if (m0) srows[warp][__popc(b0 & lt)] = i0;
    if (m1) srows[warp][c0 + __popc(b1 & lt)] = i1;
    __syncwarp();

    float4 a0 = make_float4(0.f,0.f,0.f,0.f);
    float4 a1 = a0, a2 = a0, a3 = a0;

    const int nfull8 = cnt & ~7;        // rows covered by full chunks

    // Prefetch first chunk's indices (unused if nfull8 == 0).
    int r0 = srows[warp][0], r1 = srows[warp][1];
    int r2 = srows[warp][2], r3 = srows[warp][3];
    int r4 = srows[warp][4], r5 = srows[warp][5];
    int r6 = srows[warp][6], r7 = srows[warp][7];

    for (int j = 0; j < nfull8; j += 8) {
        // 8 independent gathers in flight per warp.
        float4 f0 = __ldg(&feat[(size_t)r0 * D_VEC + lane]);
        float4 f1 = __ldg(&feat[(size_t)r1 * D_VEC + lane]);
        float4 f2 = __ldg(&feat[(size_t)r2 * D_VEC + lane]);
        float4 f3 = __ldg(&feat[(size_t)r3 * D_VEC + lane]);
        float4 f4 = __ldg(&feat[(size_t)r4 * D_VEC + lane]);
        float4 f5 = __ldg(&feat[(size_t)r5 * D_VEC + lane]);
        float4 f6 = __ldg(&feat[(size_t)r6 * D_VEC + lane]);
        float4 f7 = __ldg(&feat[(size_t)r7 * D_VEC + lane]);

        // Prefetch next chunk's indices while the gathers are in flight.
        if (j + 8 < nfull8) {
            r0 = srows[warp][j+8],  r1 = srows[warp][j+9];
            r2 = srows[warp][j+10], r3 = srows[warp][j+11];
            r4 = srows[warp][j+12], r5 = srows[warp][j+13];
            r6 = srows[warp][j+14], r7 = srows[warp][j+15];
        }

        // Dual consumer arms keep f0..f7 live across the branch -> ptxas
        // front-batches the loads. The weighted arm is dynamically dead
        // (loop covers only full chunks) but must remain for that effect.
        if (j + 8 <= cnt) {
            a0.x += f0.x; a0.y += f0.y; a0.z += f0.z; a0.w += f0.w;
            a1.x += f1.x; a1.y += f1.y; a1.z += f1.z; a1.w += f1.w;
            a2.x += f2.x; a2.y += f2.y; a2.z += f2.z; a2.w += f2.w;
            a3.x += f3.x; a3.y += f3.y; a3.z += f3.z; a3.w += f3.w;
            a0.x += f4.x; a0.y += f4.y; a0.z += f4.z; a0.w += f4.w;
            a1.x += f5.x; a1.y += f5.y; a1.z += f5.z; a1.w += f5.w;
            a2.x += f6.x; a2.y += f6.y; a2.z += f6.z; a2.w += f6.w;
            a3.x += f7.x; a3.y += f7.y; a3.z += f7.z; a3.w += f7.w;
        } else {
            float w = 0.5f;   // never executed; keeps both arms alive
            a0.x += w*f0.x; a0.y += w*f0.y; a0.z += w*f0.z; a0.w += w*f0.w;
            a1.x += w*f1.x; a1.y += w*f1.y; a1.z += w*f1.z; a1.w += w*f1.w;
            a2.x += w*f2.x; a2.y += w*f2.y; a2.z += w*f2.z; a2.w += w*f2.w;
            a3.x += w*f3.x; a3.y += w*f3.y; a3.z += w*f3.z; a3.w += w*f3.w;
            a0.x += w*f4.x; a0.y += w*f4.y; a0.z += w*f4.z; a0.w += w*f4.w;
            a1.x += w*f5.x; a1.y += w*f5.y; a1.z += w*f5.z; a1.w += w*f5.w;
            a2.x += w*f6.x; a2.y += w*f6.y; a2.z += w*f6.z; a2.w += w*f6.w;
            a3.x += w*f7.x; a3.y += w*f7.y; a3.z += w*f7.z; a3.w += w*f7.w;
        }
    }

    // Tail: rem in 1..7 rows, predicated loads (no traffic when off).
    const int rem = cnt & 7;
    if (rem) {
        const float4 z = make_float4(0.f, 0.f, 0.f, 0.f);
        int t0 = srows[warp][nfull8 + 0];
        int t1 = (rem > 1) ? srows[warp][nfull8 + 1] : 0;
        int t2 = (rem > 2) ? srows[warp][nfull8 + 2] : 0;
        int t3 = (rem > 3) ? srows[warp][nfull8 + 3] : 0;
        int t4 = (rem > 4) ? srows[warp][nfull8 + 4] : 0;
        int t5 = (rem > 5) ? srows[warp][nfull8 + 5] : 0;
        int t6 = (rem > 6) ? srows[warp][nfull8 + 6] : 0;

        float4 g0 = __ldg(&feat[(size_t)t0 * D_VEC + lane]);
        float4 g1 = z; if (rem > 1) g1 = __ldg(&feat[(size_t)t1 * D_VEC + lane]);
        float4 g2 = z; if (rem > 2) g2 = __ldg(&feat[(size_t)t2 * D_VEC + lane]);
        float4 g3 = z; if (rem > 3) g3 = __ldg(&feat[(size_t)t3 * D_VEC + lane]);
        float4 g4 = z; if (rem > 4) g4 = __ldg(&feat[(size_t)t4 * D_VEC + lane]);
        float4 g5 = z; if (rem > 5) g5 = __ldg(&feat[(size_t)t5 * D_VEC + lane]);
        float4 g6 = z; if (rem > 6) g6 = __ldg(&feat[(size_t)t6 * D_VEC + lane]);

        a0.x += g0.x; a0.y += g0.y; a0.z += g0.z; a0.w += g0.w;
        a1.x += g1.x; a1.y += g1.y; a1.z += g1.z; a1.w += g1.w;
        a2.x += g2.x; a2.y += g2.y; a2.z += g2.z; a2.w += g2.w;
        a3.x += g3.x; a3.y += g3.y; a3.z += g3.z; a3.w += g3.w;
        a0.x += g4.x; a0.y += g4.y; a0.z += g4.z; a0.w += g4.w;
        a1.x += g5.x; a1.y += g5.y; a1.z += g5.z; a1.w += g5.w;
        a2.x += g6.x; a2.y += g6.y; a2.z += g6.z; a2.w += g6.w;
    }

    const float inv = 1.0f / (float)cnt;
    float4 r;
    r.x = (a0.x + a1.x + a2.x + a3.x) * inv;
    r.y = (a0.y + a1.y + a2.y + a3.y) * inv;
    r.z = (a0.z + a1.z + a2.z + a3.z) * inv;
    r.w = (a0.w + a1.w + a2.w + a3.w) * inv;
    out[(size_t)gwarp * D_VEC + lane] = r;
}

extern "C" void kernel_launch(void* const* d_in, const int* in_sizes, int n_in,
                              void* d_out, int out_size)
{
    const float* feat  = (const float*)d_in[0];
    const void*  nidx  = d_in[1];
    const void*  nmask = d_in[2];
    float* out = (float*)d_out;

    int n_nodes = in_sizes[1] / K_NEIGH;   // 10000

    const int threads = 32 * WARPS_PER_BLOCK;
    int blocks = (n_nodes + WARPS_PER_BLOCK - 1) / WARPS_PER_BLOCK;
    mean_agg_kernel<<<blocks, threads>>>(
        (const float4*)feat, nidx, nmask, (float4*)out, n_nodes);
}